// round 6
// baseline (speedup 1.0000x reference)
#include <cuda_runtime.h>
#include <cstdint>

// ---------------- problem constants ----------------
#define HS      250          // sender hidden
#define HR      100          // receiver hidden
#define NV      40           // vocab (EOS = 39)
#define MAXLEN  30
#define IN_N    4096
#define OUT_N   262144

// ---------------- scratch (device globals; no allocation) ----------------
__device__ __align__(16) float g_h0[256];
__device__ __align__(16) float g_hR[112];
__device__ float g_part[32768];
__device__ float g_inv_d;

// ---------------- helpers ----------------
__device__ __forceinline__ float sigf(float x) { return 1.0f / (1.0f + expf(-x)); }

__device__ __forceinline__ float warp_red(float p) {
    p += __shfl_down_sync(0xffffffffu, p, 16);
    p += __shfl_down_sync(0xffffffffu, p, 8);
    p += __shfl_down_sync(0xffffffffu, p, 4);
    p += __shfl_down_sync(0xffffffffu, p, 2);
    p += __shfl_down_sync(0xffffffffu, p, 1);
    return p;
}

__device__ __forceinline__ uint32_t smem_u32(const void* p) {
    return (uint32_t)__cvta_generic_to_shared(p);
}

#define CLUSTER_SYNC() do {                                           \
    asm volatile("barrier.cluster.arrive.aligned;" ::: "memory");     \
    asm volatile("barrier.cluster.wait.aligned;"   ::: "memory");     \
} while (0)

// ---------------- kernel 1: h0 = relu(W_s1 @ x + b_s1) ----------------
__global__ void h0_kernel(const float* __restrict__ Ws1,
                          const float* __restrict__ bs1,
                          const float* __restrict__ x) {
    int row = blockIdx.x, tid = threadIdx.x;
    const float4* w  = reinterpret_cast<const float4*>(Ws1 + (size_t)row * IN_N);
    const float4* xv = reinterpret_cast<const float4*>(x);
    float acc = 0.f;
    #pragma unroll 4
    for (int i = tid; i < IN_N / 4; i += 256) {
        float4 a = w[i], b = xv[i];
        acc += a.x * b.x + a.y * b.y + a.z * b.z + a.w * b.w;
    }
    __shared__ float red[8];
    acc = warp_red(acc);
    if ((tid & 31) == 0) red[tid >> 5] = acc;
    __syncthreads();
    if (tid < 8) {
        float s = red[tid];
        for (int o = 4; o; o >>= 1) s += __shfl_down_sync(0xffu, s, o);
        if (tid == 0) g_h0[row] = fmaxf(s + bs1[row], 0.f);
    }
}

// ---------------- kernel 2: sequential sender + receiver (cluster of 8) ----
// SMEM float offsets --- sender phase (rows padded to 256 floats):
#define OFF_WHH   0                       // 128 x 256              = 32768
#define OFF_WIH   32768                   // 128 x 40               =  5120
#define OFF_WP    37888                   // 40 x 256               = 10240
#define OFF_BIA   48128                   // 128
#define OFF_BP    48256                   // 40
#define OFF_GUM   48296                   // 30*40 = 1200
#define OFF_HFULL 49496                   // 256 (16B aligned)
#define OFF_HPUB  49752                   // 2 x 32
#define OFF_CST   49816                   // 32
#define OFF_GAT   49848                   // 128
#define OFF_LOG   49976                   // 48
// receiver phase (CTA0 only, after cluster barrier; reuses region):
#define OFF_WHH2  0                       // 400 x 102              = 40800
#define OFF_UCOL  40800                   // 30 x 400               = 12000
#define OFF_B2    52800                   // 400
#define OFF_G2    53200                   // 400
#define OFF_HR    53600                   // 112
#define OFF_CR    53712                   // 112
#define OFF_MSG   53824                   // 32 ints (beyond both phases)
#define OFF_IDX   53856
#define SM_FLOATS 53864
#define SMEM_BYTES (SM_FLOATS * 4)        // 215456 B

__global__ void __cluster_dims__(8, 1, 1) __launch_bounds__(256, 1)
seq_kernel(const float* __restrict__ gumbel,
           const float* __restrict__ Wih1, const float* __restrict__ Whh1,
           const float* __restrict__ bih1, const float* __restrict__ bhh1,
           const float* __restrict__ Wp,   const float* __restrict__ bp,
           const float* __restrict__ Wih2, const float* __restrict__ Whh2,
           const float* __restrict__ bih2, const float* __restrict__ bhh2) {
    extern __shared__ float sm[];
    int* smi = reinterpret_cast<int*>(sm);
    const int tid  = threadIdx.x;
    const int rank = blockIdx.x;                  // cluster rank (grid == cluster)
    const int lane = tid & 31;
    const int wid  = tid >> 5;

    // ---- hidden-unit partition: CTA r owns hidden [32r, 32r+NH) ----
    const int NH = (rank < 7) ? 32 : (HS - 7 * 32);   // 32 or 26
    const int H0 = rank * 32;
    const int G  = 4 * NH;                            // gate rows owned (<=128)

    // ---- stage sender weights: fixed k per thread, rows in flight (MLP>=4) ----
    {
        const int k = tid;
        for (int gg = 0; gg < 4; ++gg) {
            #pragma unroll 4
            for (int j = 0; j < NH; ++j) {
                int r = gg * NH + j;
                int grow = 250 * gg + H0 + j;
                sm[OFF_WHH + (r << 8) + k] =
                    (k < HS) ? Whh1[(size_t)grow * HS + k] : 0.f;
                if (k < NV) sm[OFF_WIH + r * NV + k] = Wih1[grow * NV + k];
                if (k == NV) sm[OFF_BIA + r] = bih1[grow] + bhh1[grow];
            }
        }
        #pragma unroll 4
        for (int r = 0; r < NV; ++r)
            sm[OFF_WP + (r << 8) + k] = (k < HS) ? Wp[r * HS + k] : 0.f;
    }
    if (tid < NV) sm[OFF_BP + tid] = bp[tid];
    #pragma unroll 4
    for (int i = tid; i < MAXLEN * NV; i += 256) sm[OFF_GUM + i] = gumbel[i];
    sm[OFF_HFULL + tid] = (tid < HS) ? g_h0[tid] : 0.f;
    if (tid < 32)  sm[OFF_CST + tid] = 0.f;
    if (tid < 16)  sm[OFF_LOG + 32 + tid] = -1e30f;   // pad (never max)
    __syncthreads();

    // ---- sender loop: h held in registers (lane owns h[8L..8L+7]) ----
    float4 ha = *reinterpret_cast<const float4*>(&sm[OFF_HFULL + 8 * lane]);
    float4 hb = *reinterpret_cast<const float4*>(&sm[OFF_HFULL + 8 * lane + 4]);
    int idx_prev = -1;
    int parity   = 0;
    int Lmsg     = 0;

    for (int t = 0; t < MAXLEN; ++t) {
        // gates: warp per row, conflict-free float4 loads, shfl reduce
        #pragma unroll 2
        for (int row = wid; row < G; row += 8) {
            const float4* w4 =
                reinterpret_cast<const float4*>(&sm[OFF_WHH + (row << 8) + 8 * lane]);
            float4 a = w4[0], b = w4[1];
            float p = a.x * ha.x + a.y * ha.y + a.z * ha.z + a.w * ha.w
                    + b.x * hb.x + b.y * hb.y + b.z * hb.z + b.w * hb.w;
            p = warp_red(p);
            if (lane == 0) {
                p += sm[OFF_BIA + row];
                if (idx_prev >= 0) p += sm[OFF_WIH + row * NV + idx_prev];
                sm[OFF_GAT + row] = p;
            }
        }
        __syncthreads();
        // per-hidden LSTM update, publish new h slice
        if (tid < NH) {
            float gi = sm[OFF_GAT + tid];
            float gf = sm[OFF_GAT + NH + tid];
            float gz = sm[OFF_GAT + 2 * NH + tid];
            float go = sm[OFF_GAT + 3 * NH + tid];
            float c  = sm[OFF_CST + tid];
            float cn = sigf(gf) * c + sigf(gi) * tanhf(gz);
            float hn = sigf(go) * tanhf(cn);
            sm[OFF_CST + tid] = cn;
            sm[OFF_HPUB + parity * 32 + tid] = hn;
        }
        CLUSTER_SYNC();
        // gather full new h from all 8 CTAs (DSMEM pull)
        if (tid < HS) {
            int owner = tid >> 5, loc = tid & 31;
            uint32_t la = smem_u32(&sm[OFF_HPUB + parity * 32 + loc]);
            uint32_t ra;
            asm("mapa.shared::cluster.u32 %0, %1, %2;" : "=r"(ra) : "r"(la), "r"(owner));
            float v;
            asm volatile("ld.shared::cluster.f32 %0, [%1];" : "=f"(v) : "r"(ra));
            sm[OFF_HFULL + tid] = v;
        }
        __syncthreads();
        ha = *reinterpret_cast<const float4*>(&sm[OFF_HFULL + 8 * lane]);
        hb = *reinterpret_cast<const float4*>(&sm[OFF_HFULL + 8 * lane + 4]);
        // logits (replicated in every CTA): same warp-per-row scheme
        for (int rr = wid; rr < NV; rr += 8) {
            const float4* w4 =
                reinterpret_cast<const float4*>(&sm[OFF_WP + (rr << 8) + 8 * lane]);
            float4 a = w4[0], b = w4[1];
            float p = a.x * ha.x + a.y * ha.y + a.z * ha.z + a.w * ha.w
                    + b.x * hb.x + b.y * hb.y + b.z * hb.z + b.w * hb.w;
            p = warp_red(p);
            if (lane == 0)
                sm[OFF_LOG + rr] = p + sm[OFF_BP + rr] + sm[OFF_GUM + t * NV + rr];
        }
        __syncthreads();
        // argmax over 40 (first-max tie-break, matching jnp.argmax)
        if (wid == 0) {
            float v = sm[OFF_LOG + lane];
            int bi = lane;
            {
                float v2 = sm[OFF_LOG + 32 + lane];   // lanes 8..31 see -1e30 pad
                int   i2 = 32 + lane;
                if (lane < 8 && v2 > v) { v = v2; bi = i2; }
            }
            for (int o = 16; o; o >>= 1) {
                float ov = __shfl_down_sync(0xffffffffu, v, o);
                int   oi = __shfl_down_sync(0xffffffffu, bi, o);
                if (ov > v || (ov == v && oi < bi)) { v = ov; bi = oi; }
            }
            if (lane == 0) smi[OFF_IDX] = bi;
        }
        __syncthreads();
        int idx = smi[OFF_IDX];
        bool last = (t == MAXLEN - 1);
        if (rank == 0 && tid == 0) smi[OFF_MSG + t] = last ? (NV - 1) : idx;
        if (idx == NV - 1 || last) { Lmsg = t + 1; break; }
        idx_prev = idx;
        parity ^= 1;
    }

    // All CTAs must pass this barrier before CTA0 reuses SMEM (a slow peer's
    // final DSMEM gather must not race the receiver's overwrites).
    CLUSTER_SYNC();
    if (rank != 0) return;

    // ---- receiver (CTA0 only): stage W_hh2 + per-step input columns ----
    #pragma unroll 4
    for (int i = tid; i < 400 * HR; i += 256) {
        int row = i / HR, k = i - row * HR;
        sm[OFF_WHH2 + row * 102 + k] = Whh2[i];
    }
    for (int i = tid; i < 400; i += 256) sm[OFF_B2 + i] = bih2[i] + bhh2[i];
    __syncthreads();   // MSG visible to all threads before ucol gather
    #pragma unroll 4
    for (int i = tid; i < Lmsg * 400; i += 256) {
        int tt = i / 400, row = i - tt * 400;
        sm[OFF_UCOL + i] = Wih2[row * NV + smi[OFF_MSG + tt]];
    }
    if (tid < 112) { sm[OFF_HR + tid] = 0.f; sm[OFF_CR + tid] = 0.f; }
    __syncthreads();

    for (int t = 0; t < Lmsg; ++t) {
        for (int row = tid; row < 400; row += 256) {
            float acc = sm[OFF_B2 + row] + sm[OFF_UCOL + t * 400 + row];
            const float2* wr2 = reinterpret_cast<const float2*>(&sm[OFF_WHH2 + row * 102]);
            const float2* h2  = reinterpret_cast<const float2*>(&sm[OFF_HR]);
            #pragma unroll 10
            for (int k = 0; k < HR / 2; ++k) {
                float2 a = wr2[k], b = h2[k];
                acc += a.x * b.x + a.y * b.y;
            }
            sm[OFF_G2 + row] = acc;
        }
        __syncthreads();
        if (tid < HR) {
            float gi = sm[OFF_G2 + tid];
            float gf = sm[OFF_G2 + HR + tid];
            float gz = sm[OFF_G2 + 2 * HR + tid];
            float go = sm[OFF_G2 + 3 * HR + tid];
            float c  = sm[OFF_CR + tid];
            float cn = sigf(gf) * c + sigf(gi) * tanhf(gz);
            sm[OFF_CR + tid] = cn;
            sm[OFF_HR + tid] = sigf(go) * tanhf(cn);
        }
        __syncthreads();
    }
    if (tid < HR) g_hR[tid] = sm[OFF_HR + tid];
}

// ---------------- kernel 3: warp-per-row logits -> exp + block partials ----
__global__ void __launch_bounds__(256)
out_kernel(const float* __restrict__ Wr, const float* __restrict__ br,
           float* __restrict__ out) {
    __shared__ float4 h4s[32];
    __shared__ float red[8];
    int tid = threadIdx.x, lane = tid & 31, wid = tid >> 5;
    if (tid < 32) {
        float4 v = make_float4(0.f, 0.f, 0.f, 0.f);
        if (tid < 25) v = *reinterpret_cast<const float4*>(g_hR + 4 * tid);
        h4s[tid] = v;
    }
    __syncthreads();

    int row = blockIdx.x * 8 + wid;
    float p = 0.f;
    if (lane < 25) {
        float4 w = *reinterpret_cast<const float4*>(Wr + (size_t)row * HR + 4 * lane);
        float4 h = h4s[lane];
        p = w.x * h.x + w.y * h.y + w.z * h.z + w.w * h.w;
    }
    p = warp_red(p);
    if (lane == 0) {
        // logits are tiny (weights ~N(0,0.05^2)); exp without max-shift is safe
        float v = expf(p + br[row]);
        out[row] = v;
        red[wid] = v;
    }
    __syncthreads();
    if (tid < 8) {
        float s = red[tid];
        s += __shfl_down_sync(0xffu, s, 4);
        s += __shfl_down_sync(0xffu, s, 2);
        s += __shfl_down_sync(0xffu, s, 1);
        if (tid == 0) g_part[blockIdx.x] = s;
    }
}

// ---------------- kernel 4: deterministic total sum -> 1/sum ---------------
__global__ void __launch_bounds__(1024)
sum_kernel() {
    __shared__ float red[32];
    int tid = threadIdx.x, lane = tid & 31, wid = tid >> 5;
    float s = 0.f;
    #pragma unroll
    for (int j = 0; j < 32; ++j) s += g_part[tid + 1024 * j];
    s = warp_red(s);
    if (lane == 0) red[wid] = s;
    __syncthreads();
    if (tid < 32) {
        float t2 = red[tid];
        t2 = warp_red(t2);
        if (tid == 0) g_inv_d = 1.0f / t2;
    }
}

// ---------------- kernel 5: normalize ----------------
__global__ void __launch_bounds__(256)
scale_kernel(float* __restrict__ out) {
    int i = blockIdx.x * 256 + threadIdx.x;
    out[i] *= g_inv_d;
}

// ---------------- launch ----------------
extern "C" void kernel_launch(void* const* d_in, const int* in_sizes, int n_in,
                              void* d_out, int out_size) {
    const float* x     = (const float*)d_in[0];
    const float* gum   = (const float*)d_in[1];
    const float* Ws1   = (const float*)d_in[2];
    const float* bs1   = (const float*)d_in[3];
    const float* Wih1  = (const float*)d_in[4];
    const float* Whh1  = (const float*)d_in[5];
    const float* bih1  = (const float*)d_in[6];
    const float* bhh1  = (const float*)d_in[7];
    const float* Wp    = (const float*)d_in[8];
    const float* bp    = (const float*)d_in[9];
    const float* Wih2  = (const float*)d_in[10];
    const float* Whh2  = (const float*)d_in[11];
    const float* bih2  = (const float*)d_in[12];
    const float* bhh2  = (const float*)d_in[13];
    const float* Wr    = (const float*)d_in[14];
    const float* br    = (const float*)d_in[15];
    float* out = (float*)d_out;

    cudaFuncSetAttribute(seq_kernel, cudaFuncAttributeMaxDynamicSharedMemorySize,
                         SMEM_BYTES);

    h0_kernel<<<HS, 256>>>(Ws1, bs1, x);
    seq_kernel<<<8, 256, SMEM_BYTES>>>(gum, Wih1, Whh1, bih1, bhh1, Wp, bp,
                                       Wih2, Whh2, bih2, bhh2);
    out_kernel<<<OUT_N / 8, 256>>>(Wr, br, out);
    sum_kernel<<<1, 1024>>>();
    scale_kernel<<<OUT_N / 256, 256>>>(out);
}

// round 10
// speedup vs baseline: 1.2539x; 1.2539x over previous
#include <cuda_runtime.h>
#include <cstdint>

// ---------------- problem constants ----------------
#define HS      250          // sender hidden
#define HR      100          // receiver hidden
#define NV      40           // vocab (EOS = 39)
#define MAXLEN  30
#define IN_N    4096
#define OUT_N   262144

#define NSND    7            // sender CTAs (ranks 0..6); rank 7 = receiver
#define NHMX    36           // max hidden units per sender CTA (7*36 >= 250)

// ---------------- scratch (device globals; no allocation) ----------------
__device__ __align__(16) float g_h0[256];
__device__ __align__(16) float g_hR[112];
__device__ float g_part[4096];
__device__ float g_inv_d;

// ---------------- helpers ----------------
__device__ __forceinline__ float sigf(float x) { return 1.0f / (1.0f + expf(-x)); }

__device__ __forceinline__ float warp_red(float p) {
    p += __shfl_down_sync(0xffffffffu, p, 16);
    p += __shfl_down_sync(0xffffffffu, p, 8);
    p += __shfl_down_sync(0xffffffffu, p, 4);
    p += __shfl_down_sync(0xffffffffu, p, 2);
    p += __shfl_down_sync(0xffffffffu, p, 1);
    return p;
}

__device__ __forceinline__ uint32_t smem_u32(const void* p) {
    return (uint32_t)__cvta_generic_to_shared(p);
}

#define CLUSTER_SYNC() do {                                           \
    asm volatile("barrier.cluster.arrive.aligned;" ::: "memory");     \
    asm volatile("barrier.cluster.wait.aligned;"   ::: "memory");     \
} while (0)

// ---------------- kernel 1: h0 = relu(W_s1 @ x + b_s1) ----------------
__global__ void h0_kernel(const float* __restrict__ Ws1,
                          const float* __restrict__ bs1,
                          const float* __restrict__ x) {
    int row = blockIdx.x, tid = threadIdx.x;
    const float4* w  = reinterpret_cast<const float4*>(Ws1 + (size_t)row * IN_N);
    const float4* xv = reinterpret_cast<const float4*>(x);
    float acc = 0.f;
    #pragma unroll 4
    for (int i = tid; i < IN_N / 4; i += 256) {
        float4 a = w[i], b = xv[i];
        acc += a.x * b.x + a.y * b.y + a.z * b.z + a.w * b.w;
    }
    __shared__ float red[8];
    acc = warp_red(acc);
    if ((tid & 31) == 0) red[tid >> 5] = acc;
    __syncthreads();
    if (tid < 8) {
        float s = red[tid];
        for (int o = 4; o; o >>= 1) s += __shfl_down_sync(0xffu, s, o);
        if (tid == 0) g_h0[row] = fmaxf(s + bs1[row], 0.f);
    }
}

// ---------------- kernel 2: cluster of 8 = 7 sender CTAs + 1 receiver -----
// SMEM float offsets --- sender CTAs (ranks 0..6), rows padded to 256:
#define OFF_WHH   0                       // 144 x 256              = 36864
#define OFF_WIH   36864                   // 144 x 40               =  5760
#define OFF_WP    42624                   // 40 x 256               = 10240
#define OFF_BIA   52864                   // 144
#define OFF_BP    53008                   // 40
#define OFF_GUM   53048                   // 30*40 = 1200
#define OFF_HFULL 54248                   // 256 (16B aligned)
#define OFF_HPUB  54504                   // 2 x 36
#define OFF_CST   54576                   // 36
#define OFF_GAT   54612                   // 144
#define OFF_LOG   54756                   // 48
#define OFF_IDX   54804                   // int
// receiver CTA (rank 7) layout, low region (disjoint use):
#define ROFF_WT   0                       // WhhT2 [k][row]: 100x400 = 40000
#define ROFF_B2   40000                   // 400
#define ROFF_G2   40400                   // 400
#define ROFF_HR   40800                   // 128
#define ROFF_CR   40928                   // 128
// mailbox (ints), high region, present in every CTA's allocation;
// only rank 7's instance is written (remotely by rank 0) / polled:
#define OFF_MB    54808                   // 32
#define SM_FLOATS 54844
#define SMEM_BYTES (SM_FLOATS * 4)        // 219376 B

__global__ void __cluster_dims__(8, 1, 1) __launch_bounds__(256, 1)
seq_kernel(const float* __restrict__ gumbel,
           const float* __restrict__ Wih1, const float* __restrict__ Whh1,
           const float* __restrict__ bih1, const float* __restrict__ bhh1,
           const float* __restrict__ Wp,   const float* __restrict__ bp,
           const float* __restrict__ Wih2, const float* __restrict__ Whh2,
           const float* __restrict__ bih2, const float* __restrict__ bhh2) {
    extern __shared__ float sm[];
    int* smi = reinterpret_cast<int*>(sm);
    const int tid  = threadIdx.x;
    const int rank = blockIdx.x;
    const int lane = tid & 31;
    const int wid  = tid >> 5;

    if (rank < NSND) {
        // =================== SENDER CTA ===================
        const int NH = (rank < NSND - 1) ? NHMX : (HS - (NSND - 1) * NHMX); // 36 / 34
        const int H0 = rank * NHMX;
        const int G  = 4 * NH;                    // gate rows owned (<=144)

        // ---- stage weights: fixed k per thread, rows in flight ----
        {
            const int k = tid;
            for (int gg = 0; gg < 4; ++gg) {
                #pragma unroll 4
                for (int j = 0; j < NH; ++j) {
                    int r = gg * NH + j;
                    int grow = 250 * gg + H0 + j;
                    sm[OFF_WHH + (r << 8) + k] =
                        (k < HS) ? Whh1[(size_t)grow * HS + k] : 0.f;
                    if (k < NV) sm[OFF_WIH + r * NV + k] = Wih1[grow * NV + k];
                    if (k == NV) sm[OFF_BIA + r] = bih1[grow] + bhh1[grow];
                }
            }
            #pragma unroll 4
            for (int r = 0; r < NV; ++r)
                sm[OFF_WP + (r << 8) + k] = (k < HS) ? Wp[r * HS + k] : 0.f;
        }
        if (tid < NV) sm[OFF_BP + tid] = bp[tid];
        #pragma unroll 4
        for (int i = tid; i < MAXLEN * NV; i += 256) sm[OFF_GUM + i] = gumbel[i];
        sm[OFF_HFULL + tid] = (tid < HS) ? g_h0[tid] : 0.f;
        if (tid < NHMX) sm[OFF_CST + tid] = 0.f;
        if (tid < 8)    sm[OFF_LOG + 40 + tid] = -1e30f;   // argmax pad
        __syncthreads();

        // precompute remote mailbox base (rank 0 only uses it)
        uint32_t mb_remote = 0;
        if (rank == 0 && tid == 0) {
            uint32_t la = smem_u32(&smi[OFF_MB]);
            asm("mapa.shared::cluster.u32 %0, %1, %2;"
                : "=r"(mb_remote) : "r"(la), "r"(NSND));
        }

        float4 ha = *reinterpret_cast<const float4*>(&sm[OFF_HFULL + 8 * lane]);
        float4 hb = *reinterpret_cast<const float4*>(&sm[OFF_HFULL + 8 * lane + 4]);
        int idx_prev = -1;
        int parity   = 0;

        for (int t = 0; t < MAXLEN; ++t) {
            // gates: warp per row, conflict-free float4 loads, shfl reduce
            #pragma unroll 2
            for (int row = wid; row < G; row += 8) {
                const float4* w4 =
                    reinterpret_cast<const float4*>(&sm[OFF_WHH + (row << 8) + 8 * lane]);
                float4 a = w4[0], b = w4[1];
                float p = a.x * ha.x + a.y * ha.y + a.z * ha.z + a.w * ha.w
                        + b.x * hb.x + b.y * hb.y + b.z * hb.z + b.w * hb.w;
                p = warp_red(p);
                if (lane == 0) {
                    p += sm[OFF_BIA + row];
                    if (idx_prev >= 0) p += sm[OFF_WIH + row * NV + idx_prev];
                    sm[OFF_GAT + row] = p;
                }
            }
            __syncthreads();
            // per-hidden LSTM update, publish new h slice
            if (tid < NH) {
                float gi = sm[OFF_GAT + tid];
                float gf = sm[OFF_GAT + NH + tid];
                float gz = sm[OFF_GAT + 2 * NH + tid];
                float go = sm[OFF_GAT + 3 * NH + tid];
                float c  = sm[OFF_CST + tid];
                float cn = sigf(gf) * c + sigf(gi) * tanhf(gz);
                float hn = sigf(go) * tanhf(cn);
                sm[OFF_CST + tid] = cn;
                sm[OFF_HPUB + parity * NHMX + tid] = hn;
            }
            CLUSTER_SYNC();
            // gather full new h from the 7 sender CTAs (DSMEM pull)
            if (tid < HS) {
                int owner = tid / NHMX, loc = tid - owner * NHMX;
                uint32_t la = smem_u32(&sm[OFF_HPUB + parity * NHMX + loc]);
                uint32_t ra;
                asm("mapa.shared::cluster.u32 %0, %1, %2;" : "=r"(ra) : "r"(la), "r"(owner));
                float v;
                asm volatile("ld.shared::cluster.f32 %0, [%1];" : "=f"(v) : "r"(ra));
                sm[OFF_HFULL + tid] = v;
            }
            __syncthreads();
            ha = *reinterpret_cast<const float4*>(&sm[OFF_HFULL + 8 * lane]);
            hb = *reinterpret_cast<const float4*>(&sm[OFF_HFULL + 8 * lane + 4]);
            // logits (replicated in every sender CTA)
            for (int rr = wid; rr < NV; rr += 8) {
                const float4* w4 =
                    reinterpret_cast<const float4*>(&sm[OFF_WP + (rr << 8) + 8 * lane]);
                float4 a = w4[0], b = w4[1];
                float p = a.x * ha.x + a.y * ha.y + a.z * ha.z + a.w * ha.w
                        + b.x * hb.x + b.y * hb.y + b.z * hb.z + b.w * hb.w;
                p = warp_red(p);
                if (lane == 0)
                    sm[OFF_LOG + rr] = p + sm[OFF_BP + rr] + sm[OFF_GUM + t * NV + rr];
            }
            __syncthreads();
            // argmax over 40 (first-max tie-break, matching jnp.argmax)
            if (wid == 0) {
                float v = sm[OFF_LOG + lane];
                int bi = lane;
                if (lane < 16) {
                    float v2 = sm[OFF_LOG + 32 + lane];   // 40..47 = -1e30 pad
                    if (v2 > v) { v = v2; bi = 32 + lane; }
                }
                for (int o = 16; o; o >>= 1) {
                    float ov = __shfl_down_sync(0xffffffffu, v, o);
                    int   oi = __shfl_down_sync(0xffffffffu, bi, o);
                    if (ov > v || (ov == v && oi < bi)) { v = ov; bi = oi; }
                }
                if (lane == 0) smi[OFF_IDX] = bi;
            }
            __syncthreads();
            int idx = smi[OFF_IDX];
            bool last = (t == MAXLEN - 1);
            int emit = last ? (NV - 1) : idx;
            // post symbol to the receiver CTA's mailbox (one self-flagging word)
            if (rank == 0 && tid == 0)
                asm volatile("st.shared::cluster.u32 [%0], %1;"
                             :: "r"(mb_remote + 4u * t), "r"((uint32_t)(emit + 1))
                             : "memory");
            if (idx == NV - 1 || last) break;
            idx_prev = idx;
            parity ^= 1;
        }
        CLUSTER_SYNC();   // final barrier (paired with receiver's)
        return;
    }

    // =================== RECEIVER CTA (rank 7) ===================
    // stage W_hh2 transposed: WT[k][row], conflict-free float4 row-quads later
    #pragma unroll 4
    for (int i = tid; i < 400 * HR; i += 256) {
        int row = i / HR, k = i - row * HR;
        sm[ROFF_WT + k * 400 + row] = Whh2[i];
    }
    for (int i = tid; i < 400; i += 256) sm[ROFF_B2 + i] = bih2[i] + bhh2[i];
    if (tid < 128) { sm[ROFF_HR + tid] = 0.f; sm[ROFF_CR + tid] = 0.f; }
    if (tid < 32)  smi[OFF_MB + tid] = 0;     // mailbox must be zero before sync #1
    __syncthreads();

    int t = 0;
    for (;;) {
        CLUSTER_SYNC();                       // pairs with sender's in-loop sync t
        // poll mailbox slot t (written by rank 0 after this barrier)
        uint32_t mb_addr = smem_u32(&smi[OFF_MB + t]);
        uint32_t mv;
        do {
            asm volatile("ld.volatile.shared.u32 %0, [%1];" : "=r"(mv) : "r"(mb_addr));
        } while (mv == 0u);
        int sym = (int)mv - 1;

        // gates: 100 threads, 4 rows each, float4, h[k] broadcast
        if (tid < 100) {
            // input-column contribution from gmem (L2-hot after step 0)
            float u0 = Wih2[(4 * tid + 0) * NV + sym];
            float u1 = Wih2[(4 * tid + 1) * NV + sym];
            float u2 = Wih2[(4 * tid + 2) * NV + sym];
            float u3 = Wih2[(4 * tid + 3) * NV + sym];
            float4 acc = *reinterpret_cast<const float4*>(&sm[ROFF_B2 + 4 * tid]);
            acc.x += u0; acc.y += u1; acc.z += u2; acc.w += u3;
            #pragma unroll 4
            for (int k = 0; k < HR; ++k) {
                float hk = sm[ROFF_HR + k];
                float4 w = *reinterpret_cast<const float4*>(&sm[ROFF_WT + k * 400 + 4 * tid]);
                acc.x += w.x * hk; acc.y += w.y * hk;
                acc.z += w.z * hk; acc.w += w.w * hk;
            }
            *reinterpret_cast<float4*>(&sm[ROFF_G2 + 4 * tid]) = acc;
        }
        __syncthreads();
        if (tid < HR) {
            float gi = sm[ROFF_G2 + tid];
            float gf = sm[ROFF_G2 + HR + tid];
            float gz = sm[ROFF_G2 + 2 * HR + tid];
            float go = sm[ROFF_G2 + 3 * HR + tid];
            float c  = sm[ROFF_CR + tid];
            float cn = sigf(gf) * c + sigf(gi) * tanhf(gz);
            sm[ROFF_CR + tid] = cn;
            sm[ROFF_HR + tid] = sigf(go) * tanhf(cn);
        }
        __syncthreads();
        if (sym == NV - 1 || t == MAXLEN - 1) break;   // EOS forced at last step
        ++t;
    }
    CLUSTER_SYNC();                           // pairs with sender's final barrier
    if (tid < HR) g_hR[tid] = sm[ROFF_HR + tid];
}

// ---------------- kernel 3: warp handles 8 rows; exp + block partials ------
__global__ void __launch_bounds__(256)
out_kernel(const float* __restrict__ Wr, const float* __restrict__ br,
           float* __restrict__ out) {
    __shared__ float4 h4s[32];
    __shared__ float red[8];
    int tid = threadIdx.x, lane = tid & 31, wid = tid >> 5;
    if (tid < 32) {
        float4 v = make_float4(0.f, 0.f, 0.f, 0.f);
        if (tid < 25) v = *reinterpret_cast<const float4*>(g_hR + 4 * tid);
        h4s[tid] = v;
    }
    __syncthreads();

    int row0 = blockIdx.x * 64 + wid * 8;
    float4 h = h4s[lane];                 // zeros for lanes 25..31
    float4 w[8];
    #pragma unroll
    for (int j = 0; j < 8; ++j) {
        w[j] = make_float4(0.f, 0.f, 0.f, 0.f);
        if (lane < 25)
            w[j] = *reinterpret_cast<const float4*>(
                Wr + (size_t)(row0 + j) * HR + 4 * lane);
    }
    float wsum = 0.f;
    #pragma unroll
    for (int j = 0; j < 8; ++j) {
        float p = w[j].x * h.x + w[j].y * h.y + w[j].z * h.z + w[j].w * h.w;
        p = warp_red(p);
        if (lane == 0) {
            // logits tiny (weights ~N(0,0.05^2)); exp without max-shift is safe
            float v = expf(p + br[row0 + j]);
            out[row0 + j] = v;
            wsum += v;
        }
    }
    if (lane == 0) red[wid] = wsum;
    __syncthreads();
    if (tid < 8) {
        float s = red[tid];
        s += __shfl_down_sync(0xffu, s, 4);
        s += __shfl_down_sync(0xffu, s, 2);
        s += __shfl_down_sync(0xffu, s, 1);
        if (tid == 0) g_part[blockIdx.x] = s;
    }
}

// ---------------- kernel 4: deterministic total sum -> 1/sum ---------------
__global__ void __launch_bounds__(1024)
sum_kernel() {
    __shared__ float red[32];
    int tid = threadIdx.x, lane = tid & 31, wid = tid >> 5;
    float s = g_part[tid] + g_part[tid + 1024]
            + g_part[tid + 2048] + g_part[tid + 3072];
    s = warp_red(s);
    if (lane == 0) red[wid] = s;
    __syncthreads();
    if (tid < 32) {
        float t2 = red[tid];
        t2 = warp_red(t2);
        if (tid == 0) g_inv_d = 1.0f / t2;
    }
}

// ---------------- kernel 5: normalize ----------------
__global__ void __launch_bounds__(256)
scale_kernel(float* __restrict__ out) {
    int i = blockIdx.x * 256 + threadIdx.x;
    out[i] *= g_inv_d;
}

// ---------------- launch ----------------
extern "C" void kernel_launch(void* const* d_in, const int* in_sizes, int n_in,
                              void* d_out, int out_size) {
    const float* x     = (const float*)d_in[0];
    const float* gum   = (const float*)d_in[1];
    const float* Ws1   = (const float*)d_in[2];
    const float* bs1   = (const float*)d_in[3];
    const float* Wih1  = (const float*)d_in[4];
    const float* Whh1  = (const float*)d_in[5];
    const float* bih1  = (const float*)d_in[6];
    const float* bhh1  = (const float*)d_in[7];
    const float* Wp    = (const float*)d_in[8];
    const float* bp    = (const float*)d_in[9];
    const float* Wih2  = (const float*)d_in[10];
    const float* Whh2  = (const float*)d_in[11];
    const float* bih2  = (const float*)d_in[12];
    const float* bhh2  = (const float*)d_in[13];
    const float* Wr    = (const float*)d_in[14];
    const float* br    = (const float*)d_in[15];
    float* out = (float*)d_out;

    cudaFuncSetAttribute(seq_kernel, cudaFuncAttributeMaxDynamicSharedMemorySize,
                         SMEM_BYTES);

    h0_kernel<<<HS, 256>>>(Ws1, bs1, x);
    seq_kernel<<<8, 256, SMEM_BYTES>>>(gum, Wih1, Whh1, bih1, bhh1, Wp, bp,
                                       Wih2, Whh2, bih2, bhh2);
    out_kernel<<<OUT_N / 64, 256>>>(Wr, br, out);
    sum_kernel<<<1, 1024>>>();
    scale_kernel<<<OUT_N / 256, 256>>>(out);
}

// round 11
// speedup vs baseline: 1.6521x; 1.3176x over previous
#include <cuda_runtime.h>
#include <cstdint>

// ---------------- problem constants ----------------
#define HS      250          // sender hidden
#define HR      100          // receiver hidden
#define NV      40           // vocab (EOS = 39)
#define MAXLEN  30
#define IN_N    4096
#define OUT_N   262144

#define NSND    7            // sender CTAs (ranks 0..6); rank 7 = receiver
#define NHMX    36           // max hidden units per sender CTA (7*36 >= 250)

// ---------------- scratch (device globals; no allocation) ----------------
__device__ __align__(16) float g_h0[256];
__device__ __align__(16) float g_hR[112];
__device__ float g_part[4096];
__device__ float g_inv_d;

// ---------------- helpers ----------------
__device__ __forceinline__ float sigf(float x) { return 1.0f / (1.0f + expf(-x)); }

__device__ __forceinline__ float warp_red(float p) {
    p += __shfl_down_sync(0xffffffffu, p, 16);
    p += __shfl_down_sync(0xffffffffu, p, 8);
    p += __shfl_down_sync(0xffffffffu, p, 4);
    p += __shfl_down_sync(0xffffffffu, p, 2);
    p += __shfl_down_sync(0xffffffffu, p, 1);
    return p;
}

__device__ __forceinline__ uint32_t smem_u32(const void* p) {
    return (uint32_t)__cvta_generic_to_shared(p);
}

#define CLUSTER_SYNC() do {                                           \
    asm volatile("barrier.cluster.arrive.aligned;" ::: "memory");     \
    asm volatile("barrier.cluster.wait.aligned;"   ::: "memory");     \
} while (0)

// acquire-wait on local mbarrier for given phase parity
__device__ __forceinline__ void mbar_wait(uint32_t addr, uint32_t parity) {
    uint32_t done;
    do {
        asm volatile(
            "{\n\t.reg .pred p;\n\t"
            "mbarrier.try_wait.parity.acquire.cluster.shared::cta.b64 p, [%1], %2, 0x989680;\n\t"
            "selp.b32 %0, 1, 0, p;\n\t}"
            : "=r"(done) : "r"(addr), "r"(parity) : "memory");
    } while (!done);
}

// 8-lanes-per-row dot: row has 256 floats; lane sub (=lane&7) covers
// chunks i*32 + sub*4 .. +3 for i=0..7. Result valid at sub==0.
__device__ __forceinline__ float row_dot(const float* __restrict__ wbase,
                                         const float4* __restrict__ hr, int sub) {
    const float4* w4 = reinterpret_cast<const float4*>(wbase) + sub;
    float a0 = 0.f, a1 = 0.f;
    #pragma unroll
    for (int i = 0; i < 8; i += 2) {
        float4 w = w4[i * 8];
        a0 += w.x * hr[i].x + w.y * hr[i].y + w.z * hr[i].z + w.w * hr[i].w;
        float4 v = w4[(i + 1) * 8];
        a1 += v.x * hr[i + 1].x + v.y * hr[i + 1].y + v.z * hr[i + 1].z + v.w * hr[i + 1].w;
    }
    float a = a0 + a1;
    a += __shfl_down_sync(0xffffffffu, a, 4);
    a += __shfl_down_sync(0xffffffffu, a, 2);
    a += __shfl_down_sync(0xffffffffu, a, 1);
    return a;
}

// ---------------- kernel 1: h0 = relu(W_s1 @ x + b_s1) ----------------
__global__ void h0_kernel(const float* __restrict__ Ws1,
                          const float* __restrict__ bs1,
                          const float* __restrict__ x) {
    int row = blockIdx.x, tid = threadIdx.x;
    const float4* w  = reinterpret_cast<const float4*>(Ws1 + (size_t)row * IN_N);
    const float4* xv = reinterpret_cast<const float4*>(x);
    float acc = 0.f;
    #pragma unroll 4
    for (int i = tid; i < IN_N / 4; i += 256) {
        float4 a = w[i], b = xv[i];
        acc += a.x * b.x + a.y * b.y + a.z * b.z + a.w * b.w;
    }
    __shared__ float red[8];
    acc = warp_red(acc);
    if ((tid & 31) == 0) red[tid >> 5] = acc;
    __syncthreads();
    if (tid < 8) {
        float s = red[tid];
        for (int o = 4; o; o >>= 1) s += __shfl_down_sync(0xffu, s, o);
        if (tid == 0) g_h0[row] = fmaxf(s + bs1[row], 0.f);
    }
}

// ---------------- kernel 2: cluster of 8 = 7 sender CTAs + 1 receiver -----
// SMEM float offsets --- sender CTAs (ranks 0..6):
#define OFF_WHH   0                       // 144 x 256              = 36864
#define OFF_WP    36864                   // 40 x 256               = 10240
#define OFF_WIH   47104                   // 144 x 40               =  5760
#define OFF_BIA   52864                   // 144
#define OFF_BP    53008                   // 40
#define OFF_GUM   53048                   // 30*40 = 1200
#define OFF_HBUF  54248                   // 2 x 256 (double-buffered h, 16B aligned)
#define OFF_HPUB  54760                   // 36 (local slice staging, 16B aligned)
#define OFF_GAT   54796                   // 144
#define OFF_LOG   54940                   // 48 (rows 40..47 = -1e30 pad)
#define OFF_IDX   54988                   // int
#define OFF_MBAR  54990                   // mbarrier (8B, 8-aligned)
#define OFF_MB    54992                   // 32 ints (mailbox; only rank 7's used)
#define SM_FLOATS 55024
#define SMEM_BYTES (SM_FLOATS * 4)        // 220096 B

// receiver CTA (rank 7) low-region layout (disjoint from OFF_MBAR/OFF_MB):
#define ROFF_WT   0                       // WhhT2 [k][row]: 100x400 = 40000
#define ROFF_B2   40000                   // 400
#define ROFF_G2   40400                   // 400
#define ROFF_HR   40800                   // 128
#define ROFF_CR   40928                   // 128

__global__ void __cluster_dims__(8, 1, 1) __launch_bounds__(256, 1)
seq_kernel(const float* __restrict__ gumbel,
           const float* __restrict__ Wih1, const float* __restrict__ Whh1,
           const float* __restrict__ bih1, const float* __restrict__ bhh1,
           const float* __restrict__ Wp,   const float* __restrict__ bp,
           const float* __restrict__ Wih2, const float* __restrict__ Whh2,
           const float* __restrict__ bih2, const float* __restrict__ bhh2) {
    extern __shared__ float sm[];
    int* smi = reinterpret_cast<int*>(sm);
    const int tid  = threadIdx.x;
    const int rank = blockIdx.x;
    const int lane = tid & 31;
    const int wid  = tid >> 5;

    if (rank < NSND) {
        // =================== SENDER CTA ===================
        const int NH = (rank < NSND - 1) ? NHMX : (HS - (NSND - 1) * NHMX); // 36 / 34
        const int H0 = rank * NHMX;
        const int G  = 4 * NH;                    // gate rows owned (<=144)
        const int sub  = lane & 7;
        const int rsel = lane >> 3;

        // ---- stage weights (fixed k per thread, rows in flight) ----
        {
            const int k = tid;
            for (int gg = 0; gg < 4; ++gg) {
                #pragma unroll 4
                for (int j = 0; j < NH; ++j) {
                    int r = gg * NH + j;
                    int grow = 250 * gg + H0 + j;
                    sm[OFF_WHH + (r << 8) + k] =
                        (k < HS) ? Whh1[(size_t)grow * HS + k] : 0.f;
                    if (k < NV) sm[OFF_WIH + r * NV + k] = Wih1[grow * NV + k];
                    if (k == NV) sm[OFF_BIA + r] = bih1[grow] + bhh1[grow];
                }
            }
            for (int r = G; r < 144; ++r) sm[OFF_WHH + (r << 8) + k] = 0.f;
            #pragma unroll 4
            for (int r = 0; r < NV; ++r)
                sm[OFF_WP + (r << 8) + k] = (k < HS) ? Wp[r * HS + k] : 0.f;
        }
        if (tid < NV) sm[OFF_BP + tid] = bp[tid];
        #pragma unroll 4
        for (int i = tid; i < MAXLEN * NV; i += 256) sm[OFF_GUM + i] = gumbel[i];
        // h buffers: buf0 = h0, buf1 zero; pads [250..255] stay 0 forever
        sm[OFF_HBUF + tid]       = (tid < HS) ? g_h0[tid] : 0.f;
        sm[OFF_HBUF + 256 + tid] = 0.f;
        if (tid >= NH && tid < NHMX) sm[OFF_HPUB + tid] = 0.f;   // push-tail pad
        if (tid < 8)  sm[OFF_LOG + 40 + tid] = -1e30f;           // argmax pad
        if (tid == 0)
            asm volatile("mbarrier.init.shared.b64 [%0], %1;"
                         :: "r"(smem_u32(&smi[OFF_MBAR])), "r"(NSND) : "memory");
        __syncthreads();
        CLUSTER_SYNC();   // mbarriers + receiver mailbox must be visible cluster-wide

        // remote mailbox base (used by rank 0, warp 6, lane 0)
        uint32_t mb_remote;
        {
            uint32_t la = smem_u32(&smi[OFF_MB]);
            asm("mapa.shared::cluster.u32 %0, %1, %2;"
                : "=r"(mb_remote) : "r"(la), "r"(NSND));
        }

        float4 hr[8];
        float  cst = 0.f;          // cell state, thread tid<NH owns hidden unit tid
        int nbuf = 1, par = 0;     // next exchange: write HBUF[1], wait parity 0

        auto load_h = [&](int buf) {
            const float4* hb = reinterpret_cast<const float4*>(&sm[OFF_HBUF + buf * 256]);
            #pragma unroll
            for (int i = 0; i < 8; ++i) hr[i] = hb[i * 8 + sub];
        };
        auto gates_pass = [&]() {
            if (wid < 6) {
                #pragma unroll 1
                for (int p = 0; p < 6; ++p) {
                    int row = p * 24 + wid * 4 + rsel;
                    float a = row_dot(&sm[OFF_WHH + (row << 8)], hr, sub);
                    if (sub == 0 && row < G) sm[OFF_GAT + row] = a;
                }
            }
        };
        auto update_exchange = [&](int symb) {
            if (tid < NH) {
                float gi = sm[OFF_GAT + tid]          + sm[OFF_BIA + tid];
                float gf = sm[OFF_GAT + NH + tid]     + sm[OFF_BIA + NH + tid];
                float gz = sm[OFF_GAT + 2 * NH + tid] + sm[OFF_BIA + 2 * NH + tid];
                float go = sm[OFF_GAT + 3 * NH + tid] + sm[OFF_BIA + 3 * NH + tid];
                if (symb >= 0) {
                    gi += sm[OFF_WIH + tid * NV + symb];
                    gf += sm[OFF_WIH + (NH + tid) * NV + symb];
                    gz += sm[OFF_WIH + (2 * NH + tid) * NV + symb];
                    go += sm[OFF_WIH + (3 * NH + tid) * NV + symb];
                }
                float cn = sigf(gf) * cst + sigf(gi) * tanhf(gz);
                cst = cn;
                sm[OFF_HPUB + tid] = sigf(go) * tanhf(cn);
            }
            __syncthreads();
            // push slice to every sender CTA (incl. self) + release-arrive
            if (wid == 0 && lane < NSND) {
                uint32_t la = smem_u32(&sm[OFF_HBUF + nbuf * 256 + H0]);
                uint32_t lb = smem_u32(&smi[OFF_MBAR]);
                uint32_t ra, rb;
                asm("mapa.shared::cluster.u32 %0, %1, %2;" : "=r"(ra) : "r"(la), "r"(lane));
                asm("mapa.shared::cluster.u32 %0, %1, %2;" : "=r"(rb) : "r"(lb), "r"(lane));
                #pragma unroll
                for (int i = 0; i < 9; ++i) {
                    float4 v = *reinterpret_cast<const float4*>(&sm[OFF_HPUB + 4 * i]);
                    asm volatile("st.shared::cluster.v4.f32 [%0], {%1, %2, %3, %4};"
                                 :: "r"(ra + 16u * i),
                                    "f"(v.x), "f"(v.y), "f"(v.z), "f"(v.w) : "memory");
                }
                asm volatile("mbarrier.arrive.release.cluster.shared::cluster.b64 _, [%0];"
                             :: "r"(rb) : "memory");
            }
            mbar_wait(smem_u32(&smi[OFF_MBAR]), (uint32_t)par);
            load_h(nbuf);
            nbuf ^= 1; par ^= 1;
        };

        // ---- prologue: nh(0) = lstm(sos, h0); no logits yet ----
        load_h(0);
        gates_pass();
        __syncthreads();
        update_exchange(-1);

        // ---- pipelined main loop: logits(t) || Whh@h for step t+1 ----
        for (int t = 0;; ++t) {
            gates_pass();                        // warps 0..5: next step's partial
            if (wid >= 6) {                      // warps 6..7: logits + argmax
                int w = wid - 6;
                #pragma unroll 1
                for (int p = 0; p < 5; ++p) {
                    int rr = p * 8 + w * 4 + rsel;
                    float a = row_dot(&sm[OFF_WP + (rr << 8)], hr, sub);
                    if (sub == 0)
                        sm[OFF_LOG + rr] = a + sm[OFF_BP + rr] + sm[OFF_GUM + t * NV + rr];
                }
                asm volatile("bar.sync 1, 64;" ::: "memory");
                if (wid == 6) {
                    float v = sm[OFF_LOG + lane];
                    int bi = lane;
                    if (lane < 16) {
                        float v2 = sm[OFF_LOG + 32 + lane];   // 40..47 = -1e30 pad
                        if (v2 > v) { v = v2; bi = 32 + lane; }
                    }
                    #pragma unroll
                    for (int o = 16; o; o >>= 1) {
                        float ov = __shfl_down_sync(0xffffffffu, v, o);
                        int   oi = __shfl_down_sync(0xffffffffu, bi, o);
                        if (ov > v || (ov == v && oi < bi)) { v = ov; bi = oi; }
                    }
                    if (lane == 0) {
                        smi[OFF_IDX] = bi;
                        if (rank == 0) {         // mail symbol to receiver (self-flagging)
                            int emit = (t == MAXLEN - 1) ? (NV - 1) : bi;
                            asm volatile("st.shared::cluster.u32 [%0], %1;"
                                         :: "r"(mb_remote + 4u * t),
                                            "r"((uint32_t)(emit + 1)) : "memory");
                        }
                    }
                }
            }
            __syncthreads();
            int idx = smi[OFF_IDX];
            if (idx == NV - 1 || t == MAXLEN - 1) break;   // all CTAs break together
            update_exchange(idx);
        }
        CLUSTER_SYNC();   // no CTA may exit while peers could still touch its SMEM
        return;
    }

    // =================== RECEIVER CTA (rank 7) ===================
    #pragma unroll 4
    for (int i = tid; i < 400 * HR; i += 256) {
        int row = i / HR, k = i - row * HR;
        sm[ROFF_WT + k * 400 + row] = Whh2[i];     // transposed: [k][row]
    }
    for (int i = tid; i < 400; i += 256) sm[ROFF_B2 + i] = bih2[i] + bhh2[i];
    if (tid < 128) { sm[ROFF_HR + tid] = 0.f; sm[ROFF_CR + tid] = 0.f; }
    if (tid < 32)  smi[OFF_MB + tid] = 0;          // mailbox zero before cluster sync
    __syncthreads();
    CLUSTER_SYNC();                                 // pairs with senders' startup sync

    int t = 0;
    for (;;) {
        uint32_t mb_addr = smem_u32(&smi[OFF_MB + t]);
        uint32_t mv;
        do {
            asm volatile("ld.volatile.shared.u32 %0, [%1];" : "=r"(mv) : "r"(mb_addr));
        } while (mv == 0u);
        int sym = (int)mv - 1;

        if (tid < 100) {
            float u0 = Wih2[(4 * tid + 0) * NV + sym];
            float u1 = Wih2[(4 * tid + 1) * NV + sym];
            float u2 = Wih2[(4 * tid + 2) * NV + sym];
            float u3 = Wih2[(4 * tid + 3) * NV + sym];
            float4 acc = *reinterpret_cast<const float4*>(&sm[ROFF_B2 + 4 * tid]);
            acc.x += u0; acc.y += u1; acc.z += u2; acc.w += u3;
            #pragma unroll 4
            for (int k = 0; k < HR; ++k) {
                float hk = sm[ROFF_HR + k];
                float4 w = *reinterpret_cast<const float4*>(&sm[ROFF_WT + k * 400 + 4 * tid]);
                acc.x += w.x * hk; acc.y += w.y * hk;
                acc.z += w.z * hk; acc.w += w.w * hk;
            }
            *reinterpret_cast<float4*>(&sm[ROFF_G2 + 4 * tid]) = acc;
        }
        __syncthreads();
        if (tid < HR) {
            float gi = sm[ROFF_G2 + tid];
            float gf = sm[ROFF_G2 + HR + tid];
            float gz = sm[ROFF_G2 + 2 * HR + tid];
            float go = sm[ROFF_G2 + 3 * HR + tid];
            float c  = sm[ROFF_CR + tid];
            float cn = sigf(gf) * c + sigf(gi) * tanhf(gz);
            sm[ROFF_CR + tid] = cn;
            sm[ROFF_HR + tid] = sigf(go) * tanhf(cn);
        }
        __syncthreads();
        if (sym == NV - 1 || t == MAXLEN - 1) break;
        ++t;
    }
    if (tid < HR) g_hR[tid] = sm[ROFF_HR + tid];
    CLUSTER_SYNC();                                 // pairs with senders' final sync
}

// ---------------- kernel 3: warp handles 8 rows; exp + block partials ------
__global__ void __launch_bounds__(256)
out_kernel(const float* __restrict__ Wr, const float* __restrict__ br,
           float* __restrict__ out) {
    __shared__ float4 h4s[32];
    __shared__ float red[8];
    int tid = threadIdx.x, lane = tid & 31, wid = tid >> 5;
    if (tid < 32) {
        float4 v = make_float4(0.f, 0.f, 0.f, 0.f);
        if (tid < 25) v = *reinterpret_cast<const float4*>(g_hR + 4 * tid);
        h4s[tid] = v;
    }
    __syncthreads();

    int row0 = blockIdx.x * 64 + wid * 8;
    float4 h = h4s[lane];                 // zeros for lanes 25..31
    float4 w[8];
    #pragma unroll
    for (int j = 0; j < 8; ++j) {
        w[j] = make_float4(0.f, 0.f, 0.f, 0.f);
        if (lane < 25)
            w[j] = *reinterpret_cast<const float4*>(
                Wr + (size_t)(row0 + j) * HR + 4 * lane);
    }
    float wsum = 0.f;
    #pragma unroll
    for (int j = 0; j < 8; ++j) {
        float p = w[j].x * h.x + w[j].y * h.y + w[j].z * h.z + w[j].w * h.w;
        p = warp_red(p);
        if (lane == 0) {
            // logits tiny (weights ~N(0,0.05^2)); exp without max-shift is safe
            float v = expf(p + br[row0 + j]);
            out[row0 + j] = v;
            wsum += v;
        }
    }
    if (lane == 0) red[wid] = wsum;
    __syncthreads();
    if (tid < 8) {
        float s = red[tid];
        s += __shfl_down_sync(0xffu, s, 4);
        s += __shfl_down_sync(0xffu, s, 2);
        s += __shfl_down_sync(0xffu, s, 1);
        if (tid == 0) g_part[blockIdx.x] = s;
    }
}

// ---------------- kernel 4: deterministic total sum -> 1/sum ---------------
__global__ void __launch_bounds__(1024)
sum_kernel() {
    __shared__ float red[32];
    int tid = threadIdx.x, lane = tid & 31, wid = tid >> 5;
    float s = g_part[tid] + g_part[tid + 1024]
            + g_part[tid + 2048] + g_part[tid + 3072];
    s = warp_red(s);
    if (lane == 0) red[wid] = s;
    __syncthreads();
    if (tid < 32) {
        float t2 = red[tid];
        t2 = warp_red(t2);
        if (tid == 0) g_inv_d = 1.0f / t2;
    }
}

// ---------------- kernel 5: normalize ----------------
__global__ void __launch_bounds__(256)
scale_kernel(float* __restrict__ out) {
    int i = blockIdx.x * 256 + threadIdx.x;
    out[i] *= g_inv_d;
}

// ---------------- launch ----------------
extern "C" void kernel_launch(void* const* d_in, const int* in_sizes, int n_in,
                              void* d_out, int out_size) {
    const float* x     = (const float*)d_in[0];
    const float* gum   = (const float*)d_in[1];
    const float* Ws1   = (const float*)d_in[2];
    const float* bs1   = (const float*)d_in[3];
    const float* Wih1  = (const float*)d_in[4];
    const float* Whh1  = (const float*)d_in[5];
    const float* bih1  = (const float*)d_in[6];
    const float* bhh1  = (const float*)d_in[7];
    const float* Wp    = (const float*)d_in[8];
    const float* bp    = (const float*)d_in[9];
    const float* Wih2  = (const float*)d_in[10];
    const float* Whh2  = (const float*)d_in[11];
    const float* bih2  = (const float*)d_in[12];
    const float* bhh2  = (const float*)d_in[13];
    const float* Wr    = (const float*)d_in[14];
    const float* br    = (const float*)d_in[15];
    float* out = (float*)d_out;

    cudaFuncSetAttribute(seq_kernel, cudaFuncAttributeMaxDynamicSharedMemorySize,
                         SMEM_BYTES);

    h0_kernel<<<HS, 256>>>(Ws1, bs1, x);
    seq_kernel<<<8, 256, SMEM_BYTES>>>(gum, Wih1, Whh1, bih1, bhh1, Wp, bp,
                                       Wih2, Whh2, bih2, bhh2);
    out_kernel<<<OUT_N / 64, 256>>>(Wr, br, out);
    sum_kernel<<<1, 1024>>>();
    scale_kernel<<<OUT_N / 256, 256>>>(out);
}